// round 12
// baseline (speedup 1.0000x reference)
#include <cuda_runtime.h>
#include <cuda_bf16.h>
#include <cstdint>

#define TT 64
#define LL 64
#define BB 16
#define HH 256
#define NDIAG 127
#define GRID 64
#define NTHREADS 512
#define NCHUNK 16
// stage layout in u32 units: AH 2048 | AL 2048 | WH 2048 | WL 2048  = 32KB/stage
#define ST_U32 8192
#define AL_U 2048
#define WH_U 4096
#define WL_U 6144
#define SMEM_TOTAL 98304   // 3 stages; xch [128][132] overlays after mainloop

typedef unsigned long long u64;
typedef uint32_t u32;

__device__ float g_c[LL * BB * HH];          // 4 MB
__device__ float g_h[2][LL * BB * HH];       // 8 MB (double-buffered by parity)
__device__ u32 g_Wh[8 * 16 * 128 * 16];      // 1 MB  [nh][chunk][n][col] bf16x2, frag layout
__device__ u32 g_Wl[8 * 16 * 128 * 16];      // 1 MB
__device__ unsigned g_bar;

__device__ __forceinline__ float sig_(float v)  { return 1.0f / (1.0f + __expf(-v)); }
__device__ __forceinline__ float tanh_(float v) { return 2.0f / (1.0f + __expf(-2.0f * v)) - 1.0f; }

__device__ __forceinline__ void cpa16(u32 d, const void* s) {
    asm volatile("cp.async.cg.shared.global [%0], [%1], 16;" :: "r"(d), "l"(s));
}
__device__ __forceinline__ void cpcommit() { asm volatile("cp.async.commit_group;"); }
template<int N> __device__ __forceinline__ void cpwait() {
    asm volatile("cp.async.wait_group %0;" :: "n"(N));
}

__device__ __forceinline__ void mma_bf16(float* d, u32 a0, u32 a1, u32 a2, u32 a3,
                                         u32 b0, u32 b1) {
    asm("mma.sync.aligned.m16n8k16.row.col.f32.bf16.bf16.f32 "
        "{%0,%1,%2,%3},{%4,%5,%6,%7},{%8,%9},{%0,%1,%2,%3};"
        : "+f"(d[0]), "+f"(d[1]), "+f"(d[2]), "+f"(d[3])
        : "r"(a0), "r"(a1), "r"(a2), "r"(a3), "r"(b0), "r"(b1));
}

__global__ void init_kernel(const float* __restrict__ init_state) {
    int i = blockIdx.x * blockDim.x + threadIdx.x;
    if (i == 0) g_bar = 0u;
    if (i < LL * BB * HH) {
        int l = i / (BB * HH);
        int r = i - l * (BB * HH);
        g_c[i]    = init_state[(l * 2 + 0) * (BB * HH) + r];
        float h   = init_state[(l * 2 + 1) * (BB * HH) + r];
        g_h[0][i] = h;
        g_h[1][i] = h;
    }
}

// Split W into bf16 hi/lo in fragment-ready layout:
// [nh][chunk][n(128)][col(16)] where col encodes k-pair perm + swizzle.
__global__ void prep_kernel(const float* __restrict__ W) {
    int idx = blockIdx.x * blockDim.x + threadIdx.x;
    if (idx >= 8 * 16 * 128 * 16) return;
    int col = idx & 15;
    int n   = (idx >> 4) & 127;
    int c   = (idx >> 11) & 15;
    int nh  = idx >> 15;
    int cp  = col ^ ((n & 3) << 2);            // undo swizzle
    int cc  = cp & 7;
    int kp  = (cc >> 1) | ((cc & 1) << 2) | (cp & 8);   // undo pair perm
    int k   = c * 32 + kp * 2;
    int gcol = (n >> 5) * 256 + nh * 32 + (n & 31);
    float w0 = W[(size_t)k * 1024 + gcol];
    float w1 = W[(size_t)(k + 1) * 1024 + gcol];
    __nv_bfloat16 h0 = __float2bfloat16(w0);
    __nv_bfloat16 h1 = __float2bfloat16(w1);
    __nv_bfloat16 l0 = __float2bfloat16(w0 - __bfloat162float(h0));
    __nv_bfloat16 l1 = __float2bfloat16(w1 - __bfloat162float(h1));
    g_Wh[idx] = ((u32)__bfloat16_as_ushort(h1) << 16) | __bfloat16_as_ushort(h0);
    g_Wl[idx] = ((u32)__bfloat16_as_ushort(l1) << 16) | __bfloat16_as_ushort(l0);
}

__device__ __forceinline__ void ldA(float v[8], bool valid, const float* p) {
    if (valid) {
        float4 a = *(const float4*)p;
        float4 b = *(const float4*)(p + 4);
        v[0]=a.x; v[1]=a.y; v[2]=a.z; v[3]=a.w;
        v[4]=b.x; v[5]=b.y; v[6]=b.z; v[7]=b.w;
    } else {
        #pragma unroll
        for (int i = 0; i < 8; i++) v[i] = 0.0f;
    }
}

// Split+store one A row-segment (8 k values = 4 k-pairs) into stage s.
__device__ __forceinline__ void stsA(u32* smem, int s, int r, int q, const float v[8]) {
    u32* ah = smem + s * ST_U32 + r * 16;
    u32* al = ah + AL_U;
    const int kp0 = q >> 1;
    #pragma unroll
    for (int i = 0; i < 4; i++) {
        int kp = kp0 + i;
        __nv_bfloat16 h0 = __float2bfloat16(v[2*i]);
        __nv_bfloat16 h1 = __float2bfloat16(v[2*i+1]);
        __nv_bfloat16 l0 = __float2bfloat16(v[2*i]   - __bfloat162float(h0));
        __nv_bfloat16 l1 = __float2bfloat16(v[2*i+1] - __bfloat162float(h1));
        u32 hw = ((u32)__bfloat16_as_ushort(h1) << 16) | __bfloat16_as_ushort(h0);
        u32 lw = ((u32)__bfloat16_as_ushort(l1) << 16) | __bfloat16_as_ushort(l0);
        int col = ((kp & 8) | (((kp & 3) << 1) | ((kp >> 2) & 1))) ^ ((r & 3) << 2);
        ah[col] = hw;
        al[col] = lw;
    }
}

__device__ __forceinline__ void issueW(u32 sbase, int s, const u32* wsh, const u32* wsl, int c) {
    const int tid = threadIdx.x;
    cpa16(sbase + (s * ST_U32 + WH_U) * 4 + (u32)tid * 16, wsh + (size_t)c * 2048);
    cpa16(sbase + (s * ST_U32 + WL_U) * 4 + (u32)tid * 16, wsl + (size_t)c * 2048);
}

__global__ void __launch_bounds__(NTHREADS, 1)
lstm_kernel(const float* __restrict__ x, const float* __restrict__ bias,
            float* __restrict__ out) {
    extern __shared__ __align__(16) u32 smem[];
    const int tid  = threadIdx.x;
    const int w    = tid >> 5;
    const int lane = tid & 31;
    const int fg   = lane >> 2;       // fragment group row
    const int tig  = lane & 3;
    const int mrow0 = (w & 3) * 32;
    const int ncol0 = (w >> 2) * 32;
    const u32 sbase = (u32)__cvta_generic_to_shared(smem);

    for (int d = 0; d < NDIAG; d++) {
        const int l_lo = (d - (TT - 1) > 0) ? d - (TT - 1) : 0;
        const int l_hi = (d < LL - 1) ? d : LL - 1;
        const int n    = l_hi - l_lo + 1;
        const int ntiles = ((n + 7) >> 3) << 3;    // <= 64
        const float* hin  = g_h[(d + 1) & 1];
        float*       hout = g_h[d & 1];

        if ((int)blockIdx.x < ntiles) {
            const int tile   = blockIdx.x;
            const int nh     = tile & 7;
            const int l_base = l_lo + (tile >> 3) * 8;

            // A row for this thread: row r (cell ci, batch bb), k-segment q..q+7
            const int r  = tid >> 2;
            const int q  = (tid & 3) << 3;
            const int ci = r >> 4, bb = r & 15;
            const int l  = l_base + ci;
            const bool valid = (l <= l_hi);
            const int lc = valid ? l : l_hi;
            const int t  = d - lc;
            const float* pinT = ((lc == 0) ? (x + (bb * TT + t) * HH)
                                           : (hin + ((lc - 1) * BB + bb) * HH)) + q;
            const float* phT  = hin + (lc * BB + bb) * HH + q;
            const u32* wsh = g_Wh + (size_t)nh * 16 * 2048 + tid * 4;
            const u32* wsl = g_Wl + (size_t)nh * 16 * 2048 + tid * 4;

            float acc[2][4][4];
            #pragma unroll
            for (int mf = 0; mf < 2; mf++)
                #pragma unroll
                for (int nf = 0; nf < 4; nf++)
                    #pragma unroll
                    for (int e = 0; e < 4; e++) acc[mf][nf][e] = 0.0f;

            // prologue: chunks 0,1 staged; chunk2 fp32 into regs
            float v[8];
            ldA(v, valid, pinT);       stsA(smem, 0, r, q, v);
            ldA(v, valid, pinT + 32);  stsA(smem, 1, r, q, v);
            issueW(sbase, 0, wsh, wsl, 0); cpcommit();
            issueW(sbase, 1, wsh, wsl, 1); cpcommit();
            ldA(v, valid, pinT + 64);

            #pragma unroll 1
            for (int c = 0; c < NCHUNK; c++) {
                cpwait<1>();
                __syncthreads();
                if (c + 2 < NCHUNK) {
                    const int s2 = (c + 2) % 3;
                    issueW(sbase, s2, wsh, wsl, c + 2); cpcommit();
                    stsA(smem, s2, r, q, v);
                    if (c + 3 < NCHUNK) {
                        const int nc = c + 3;
                        ldA(v, valid, ((nc < 8) ? pinT + nc * 32 : phT + (nc - 8) * 32));
                    }
                } else {
                    cpcommit();
                }
                // compute chunk c from stage c%3
                const u32* st = smem + (c % 3) * ST_U32;
                #pragma unroll
                for (int ss = 0; ss < 2; ss++) {
                    u64 bh[4], bl[4];
                    #pragma unroll
                    for (int nf = 0; nf < 4; nf++) {
                        int row = ncol0 + nf * 8 + fg;
                        int col = (ss * 8 + 2 * tig) ^ ((row & 3) << 2);
                        bh[nf] = *(const u64*)(st + WH_U + row * 16 + col);
                        bl[nf] = *(const u64*)(st + WL_U + row * 16 + col);
                    }
                    #pragma unroll
                    for (int mf = 0; mf < 2; mf++) {
                        int r0 = mrow0 + mf * 16 + fg;
                        int c0 = (ss * 8 + 2 * tig) ^ ((r0 & 3) << 2);
                        u64 ah0 = *(const u64*)(st + r0 * 16 + c0);
                        u64 ah1 = *(const u64*)(st + (r0 + 8) * 16 + c0);
                        u64 al0 = *(const u64*)(st + AL_U + r0 * 16 + c0);
                        u64 al1 = *(const u64*)(st + AL_U + (r0 + 8) * 16 + c0);
                        u32 a0 = (u32)ah0, a2 = (u32)(ah0 >> 32);
                        u32 a1 = (u32)ah1, a3 = (u32)(ah1 >> 32);
                        u32 e0 = (u32)al0, e2 = (u32)(al0 >> 32);
                        u32 e1 = (u32)al1, e3 = (u32)(al1 >> 32);
                        #pragma unroll
                        for (int nf = 0; nf < 4; nf++) {
                            u32 b0 = (u32)bh[nf], b1 = (u32)(bh[nf] >> 32);
                            u32 c1 = (u32)bl[nf], c2 = (u32)(bl[nf] >> 32);
                            float* dd = acc[mf][nf];
                            mma_bf16(dd, a0, a1, a2, a3, b0, b1);
                            mma_bf16(dd, e0, e1, e2, e3, b0, b1);
                            mma_bf16(dd, a0, a1, a2, a3, c1, c2);
                        }
                    }
                }
            }

            // dump D to smem (xch overlays the stages) and run gates
            __syncthreads();
            float* xch = (float*)smem;     // [128][132]
            #pragma unroll
            for (int mf = 0; mf < 2; mf++) {
                #pragma unroll
                for (int nf = 0; nf < 4; nf++) {
                    int row = mrow0 + mf * 16 + fg;
                    int col = ncol0 + nf * 8 + 2 * tig;
                    *(float2*)&xch[row * 132 + col] =
                        make_float2(acc[mf][nf][0], acc[mf][nf][1]);
                    *(float2*)&xch[(row + 8) * 132 + col] =
                        make_float2(acc[mf][nf][2], acc[mf][nf][3]);
                }
            }
            __syncthreads();
            {
                const int hc    = tid & 31;
                const int rbase = (tid >> 5) << 3;
                const int hcol  = nh * 32 + hc;
                const float bi = bias[hcol];
                const float bj = bias[256 + hcol];
                const float bf = bias[512 + hcol];
                const float bo = bias[768 + hcol];
                #pragma unroll
                for (int j = 0; j < 8; j++) {
                    const int rr  = rbase + j;
                    const int cii = rr >> 4;
                    const int bbb = rr & 15;
                    const int ll  = l_base + cii;
                    if (ll <= l_hi) {
                        const int tt   = d - ll;
                        const int sidx = (ll * BB + bbb) * HH + hcol;
                        const float* xr = &xch[rr * 132 + hc];
                        float zi = xr[0]  + bi;
                        float zj = xr[32] + bj;
                        float zf = xr[64] + bf;
                        float zo = xr[96] + bo;
                        float cold = g_c[sidx];
                        float ncv  = sig_(zf + 1.0f) * cold + sig_(zi) * tanh_(zj);
                        float nhv  = sig_(zo) * tanh_(ncv);
                        g_c[sidx]  = ncv;
                        hout[sidx] = nhv;
                        if (ll == LL - 1) out[(bbb * TT + tt) * HH + hcol] = nhv;
                    }
                }
            }
        }

        // --- grid-wide barrier (release + L1 invalidate via membar.gpu) ---
        if (d < NDIAG - 1) {
            __threadfence();
            __syncthreads();
            if (tid == 0) {
                unsigned target = (unsigned)gridDim.x * (unsigned)(d + 1);
                atomicAdd(&g_bar, 1u);
                while (*((volatile unsigned*)&g_bar) < target) { }
            }
            __syncthreads();
        }
    }
}

extern "C" void kernel_launch(void* const* d_in, const int* in_sizes, int n_in,
                              void* d_out, int out_size) {
    const float* x    = (const float*)d_in[0];   // (B, T, H)
    const float* init = (const float*)d_in[1];   // (L, 2, B, H)
    const float* W    = (const float*)d_in[2];   // (2H, 4H)
    const float* bias = (const float*)d_in[3];   // (4H,)
    float* out        = (float*)d_out;           // (B, T, H)

    cudaFuncSetAttribute(lstm_kernel, cudaFuncAttributeMaxDynamicSharedMemorySize, SMEM_TOTAL);
    init_kernel<<<(LL * BB * HH + 255) / 256, 256>>>(init);
    prep_kernel<<<(8 * 16 * 128 * 16 + 255) / 256, 256>>>(W);
    lstm_kernel<<<GRID, NTHREADS, SMEM_TOTAL>>>(x, bias, out);
}

// round 13
// speedup vs baseline: 1.6907x; 1.6907x over previous
#include <cuda_runtime.h>
#include <cstdint>

#define TT 64
#define LL 64
#define BB 16
#define HH 256
#define NDIAG 127
#define GRID 148
#define NTHREADS 512
#define KC 128
#define NCHUNK 4
// stage: W float2[64][128] @0 (64KB) | A float[64][128] @65536 (32KB)
#define STAGE_BYTES 98304
#define A_OFF 65536
#define SMEM_TOTAL (2 * STAGE_BYTES)   // 192 KB

typedef unsigned long long u64;
typedef uint32_t u32;

__device__ float g_c[LL * BB * HH];            // 4 MB
__device__ float g_h[2][LL * BB * HH];         // 8 MB (double-buffered by parity)
__device__ float g_Wpack[8 * 4 * 8192 * 2];    // 2 MB  [nh][chunk(4)][k2(64)][col(128)] float2
__device__ unsigned g_bar;

__device__ __forceinline__ float sig_(float v)  { return 1.0f / (1.0f + __expf(-v)); }
__device__ __forceinline__ float tanh_(float v) { return 2.0f / (1.0f + __expf(-2.0f * v)) - 1.0f; }

// Packed fp32x2 FMA (SASS FFMA2)
__device__ __forceinline__ void ffma2(u64 &d, u64 a, u64 b) {
    asm("fma.rn.f32x2 %0, %1, %2, %0;" : "+l"(d) : "l"(a), "l"(b));
}
__device__ __forceinline__ float fold2(u64 p) {
    float2 f = *reinterpret_cast<float2*>(&p);
    return f.x + f.y;
}
__device__ __forceinline__ void cpa16(u32 d, const void* s) {
    asm volatile("cp.async.cg.shared.global [%0], [%1], 16;" :: "r"(d), "l"(s));
}
__device__ __forceinline__ void cpcommit() { asm volatile("cp.async.commit_group;"); }
template<int N> __device__ __forceinline__ void cpwait() {
    asm volatile("cp.async.wait_group %0;" :: "n"(N));
}

__global__ void init_kernel(const float* __restrict__ init_state) {
    int i = blockIdx.x * blockDim.x + threadIdx.x;
    if (i == 0) g_bar = 0u;
    if (i < LL * BB * HH) {
        int l = i / (BB * HH);
        int r = i - l * (BB * HH);
        g_c[i]    = init_state[(l * 2 + 0) * (BB * HH) + r];
        float h   = init_state[(l * 2 + 1) * (BB * HH) + r];
        g_h[0][i] = h;
        g_h[1][i] = h;
    }
}

// Pre-swizzle W: [nh][chunk(4)][k2(64)][g*32+hc] float2 (k-pair interleave for FFMA2)
__global__ void prep_kernel(const float* __restrict__ W) {
    int idx = blockIdx.x * blockDim.x + threadIdx.x;   // float2 index
    if (idx >= 8 * 4 * 64 * 128) return;
    int col = idx & 127;           // g*32 + hc
    int k2  = (idx >> 7) & 63;
    int c   = (idx >> 13) & 3;
    int nh  = idx >> 15;
    int k   = c * KC + (k2 << 1);
    int gcol = (col >> 5) * 256 + nh * 32 + (col & 31);
    g_Wpack[idx * 2]     = W[(size_t)k * 1024 + gcol];
    g_Wpack[idx * 2 + 1] = W[(size_t)(k + 1) * 1024 + gcol];
}

// Stage one 64KB W chunk into stage s: 128B per thread = 8 cp.async.
__device__ __forceinline__ void issueW(u32 sbase, int nh, int c, int s, int tid) {
    const float* src = g_Wpack + ((size_t)(nh * 4 + c) << 14) + tid * 32;
    u32 dst = sbase + s * STAGE_BYTES + (u32)tid * 128;
    #pragma unroll
    for (int i = 0; i < 8; i++) cpa16(dst + i * 16, src + i * 4);
}

// Stage one 32KB A chunk: 64B per thread = 4 cp.async. pin/ph pre-offset by seg.
__device__ __forceinline__ void issueA(u32 a_dst, int s, int c,
                                       const float* pin, const float* ph) {
    const float* src = (c < 2) ? (pin + c * KC) : (ph + (c - 2) * KC);
    u32 dst = a_dst + s * STAGE_BYTES;
    cpa16(dst, src); cpa16(dst + 16, src + 4);
    cpa16(dst + 32, src + 8); cpa16(dst + 48, src + 12);
}

// Per-tile body. Warps 0-7: k2 0..31; warps 8-15: k2 32..63 (split-K halves).
template<int CG>
__device__ __forceinline__ void tile_body(
    char* smem, const float* __restrict__ x,
    const float* __restrict__ bias, float* __restrict__ out,
    const float* __restrict__ hin, float* __restrict__ hout,
    int d, int l_lo, int l_hi, int tile)
{
    constexpr int RW = 2 * CG;
    const int tid = threadIdx.x;
    const int w   = tid >> 5;
    const int hc  = tid & 31;
    const int nh      = tile & 7;
    const int l_base  = l_lo + (tile >> 3) * CG;

    // --- A staging pointers (row = tid>>3, 16-float segment = (tid&7)*16) ---
    const int s_row = tid >> 3;
    const int seg   = (tid & 7) << 4;
    const int ci_s  = s_row >> 4;
    const int bb_s  = s_row & 15;
    int ls = l_base + ci_s; if (ls > l_hi) ls = l_hi;   // clamp for safe addr
    const int ts = d - ls;
    const float* pin = ((ls == 0) ? (x + (bb_s * TT + ts) * HH)
                                  : (hin + ((ls - 1) * BB + bb_s) * HH)) + seg;
    const float* ph  = hin + (ls * BB + bb_s) * HH + seg;

    const u32 sbase = (u32)__cvta_generic_to_shared(smem);
    const u32 a_dst = sbase + A_OFF + (u32)((s_row << 7) + seg) * 4;

    u64 acc[RW][4];
    #pragma unroll
    for (int j = 0; j < RW; j++)
        #pragma unroll
        for (int g = 0; g < 4; g++) acc[j][g] = 0ull;

    const int r0     = (w & 7) * RW;
    const int k2base = (w >> 3) << 5;   // 0 or 32

    // A0 (W0 was prefetched into stage 0 before the grid barrier)
    issueA(a_dst, 0, 0, pin, ph);
    cpcommit();

    // --- K mainloop: 4 chunks, double-buffered ---
    #pragma unroll 1
    for (int c = 0; c < NCHUNK; c++) {
        cpwait<0>();
        __syncthreads();                 // chunk c visible; all warps done with c-1
        if (c + 1 < NCHUNK) {
            const int sn = (c + 1) & 1;
            issueW(sbase, nh, c + 1, sn, tid);
            issueA(a_dst, sn, c + 1, pin, ph);
            cpcommit();
        }
        const float*  a  = (const float*)(smem + (c & 1) * STAGE_BYTES + A_OFF)
                           + r0 * KC + (k2base << 1);
        const float2* w2 = (const float2*)(smem + (c & 1) * STAGE_BYTES) + hc;
        #pragma unroll 4
        for (int q4 = 0; q4 < 16; q4++) {
            u64 wv[2][4];
            #pragma unroll
            for (int e = 0; e < 2; e++)
                #pragma unroll
                for (int g = 0; g < 4; g++)
                    wv[e][g] = *(const u64*)(w2 + (k2base + q4 * 2 + e) * 128 + g * 32);
            #pragma unroll
            for (int j = 0; j < RW; j++) {
                ulonglong2 ap = *(const ulonglong2*)(a + j * KC + q4 * 4);
                #pragma unroll
                for (int g = 0; g < 4; g++) ffma2(acc[j][g], ap.x, wv[0][g]);
                #pragma unroll
                for (int g = 0; g < 4; g++) ffma2(acc[j][g], ap.y, wv[1][g]);
            }
        }
    }

    // --- combine k-halves (xch overlays stage-1 W region, quiescent post-loop) ---
    __syncthreads();
    float* xch = (float*)(smem + STAGE_BYTES);
    if (w >= 8) {
        #pragma unroll
        for (int j = 0; j < RW; j++)
            #pragma unroll
            for (int g = 0; g < 4; g++)
                xch[(((w - 8) * RW) + j) * 128 + g * 32 + hc] = fold2(acc[j][g]);
    }
    __syncthreads();
    if (w < 8) {
        const int hcol = nh * 32 + hc;
        const float bi = bias[hcol];
        const float bj = bias[256 + hcol];
        const float bf = bias[512 + hcol];
        const float bo = bias[768 + hcol];
        #pragma unroll
        for (int j = 0; j < RW; j++) {
            const int row = w * RW + j;
            const int ci  = row >> 4;
            const int bb  = row & 15;
            const int l   = l_base + ci;
            if (l <= l_hi) {
                const int t    = d - l;
                const int sidx = (l * BB + bb) * HH + hcol;
                const float* xr = &xch[(w * RW + j) * 128 + hc];
                float zi = fold2(acc[j][0]) + xr[0]  + bi;
                float zj = fold2(acc[j][1]) + xr[32] + bj;
                float zf = fold2(acc[j][2]) + xr[64] + bf;
                float zo = fold2(acc[j][3]) + xr[96] + bo;
                float cold = g_c[sidx];
                float ncv  = sig_(zf + 1.0f) * cold + sig_(zi) * tanh_(zj);
                float nhv  = sig_(zo) * tanh_(ncv);
                g_c[sidx]  = ncv;
                hout[sidx] = nhv;
                if (l == LL - 1) out[(bb * TT + t) * HH + hcol] = nhv;
            }
        }
    }
}

__global__ void __launch_bounds__(NTHREADS, 1)
lstm_kernel(const float* __restrict__ x, const float* __restrict__ bias,
            float* __restrict__ out) {
    extern __shared__ __align__(16) char smem[];
    const int tid = threadIdx.x;
    const int G   = gridDim.x;
    const u32 sbase = (u32)__cvta_generic_to_shared(smem);

    // prologue: W0 prefetch for d=0 (ntiles = 8)
    if ((int)blockIdx.x < 8) issueW(sbase, blockIdx.x & 7, 0, 0, tid);
    cpcommit();

    for (int d = 0; d < NDIAG; d++) {
        const int l_lo = (d - (TT - 1) > 0) ? d - (TT - 1) : 0;
        const int l_hi = (d < LL - 1) ? d : LL - 1;
        const int n    = l_hi - l_lo + 1;
        const int CG   = (n + 17) / 18;          // 1..4 cells per M-tile
        const int ntiles = ((n + CG - 1) / CG) << 3;   // <= 144
        const float* hin  = g_h[(d + 1) & 1];
        float*       hout = g_h[d & 1];

        if ((int)blockIdx.x < ntiles) {
            const int tile = blockIdx.x;
            if      (CG == 4) tile_body<4>(smem, x, bias, out, hin, hout, d, l_lo, l_hi, tile);
            else if (CG == 3) tile_body<3>(smem, x, bias, out, hin, hout, d, l_lo, l_hi, tile);
            else if (CG == 2) tile_body<2>(smem, x, bias, out, hin, hout, d, l_lo, l_hi, tile);
            else              tile_body<1>(smem, x, bias, out, hin, hout, d, l_lo, l_hi, tile);
        }

        if (d < NDIAG - 1) {
            // cross-barrier W0 prefetch for next diagonal (state-independent)
            const int d2    = d + 1;
            const int l_lo2 = (d2 - (TT - 1) > 0) ? d2 - (TT - 1) : 0;
            const int l_hi2 = (d2 < LL - 1) ? d2 : LL - 1;
            const int n2    = l_hi2 - l_lo2 + 1;
            const int CG2   = (n2 + 17) / 18;
            const int ntiles2 = ((n2 + CG2 - 1) / CG2) << 3;
            if ((int)blockIdx.x < ntiles2) issueW(sbase, blockIdx.x & 7, 0, 0, tid);
            cpcommit();

            // grid-wide barrier (release + L1 invalidate via membar.gpu)
            __threadfence();
            __syncthreads();
            if (tid == 0) {
                unsigned target = (unsigned)G * (unsigned)(d + 1);
                atomicAdd(&g_bar, 1u);
                while (*((volatile unsigned*)&g_bar) < target) { }
            }
            __syncthreads();
        }
    }
}

extern "C" void kernel_launch(void* const* d_in, const int* in_sizes, int n_in,
                              void* d_out, int out_size) {
    const float* x    = (const float*)d_in[0];   // (B, T, H)
    const float* init = (const float*)d_in[1];   // (L, 2, B, H)
    const float* W    = (const float*)d_in[2];   // (2H, 4H)
    const float* bias = (const float*)d_in[3];   // (4H,)
    float* out        = (float*)d_out;           // (B, T, H)

    cudaFuncSetAttribute(lstm_kernel, cudaFuncAttributeMaxDynamicSharedMemorySize, SMEM_TOTAL);
    init_kernel<<<(LL * BB * HH + 255) / 256, 256>>>(init);
    prep_kernel<<<(8 * 4 * 64 * 128 + 255) / 256, 256>>>(W);
    lstm_kernel<<<GRID, NTHREADS, SMEM_TOTAL>>>(x, bias, out);
}

// round 14
// speedup vs baseline: 2.0875x; 1.2347x over previous
#include <cuda_runtime.h>
#include <cstdint>

#define TT 64
#define LL 64
#define BB 16
#define HH 256
#define NDIAG 127
#define GRID 148
#define NTHREADS 512
#define KC 64
#define NCHUNK 8
// 3 stages x 48KB: W[32][128]f2 @ +0 (32KB), A[64][64]f @ +32768 (16KB)
#define STAGE_BYTES 49152
#define A_OFF 32768
#define SMEM_TOTAL (3 * STAGE_BYTES)

typedef unsigned long long u64;
typedef uint32_t u32;

// Persistent state (device globals: allocation-free scratch)
__device__ float g_c[LL * BB * HH];              // 4 MB
__device__ float g_h[2][LL * BB * HH];           // 8 MB (double-buffered by parity)
__device__ float g_Wpack[8 * 8 * 32 * 128 * 2];  // 2 MB  [nh][chunk][k2][g*32+hc] float2
__device__ unsigned g_bar;

__device__ __forceinline__ float sig_(float v)  { return 1.0f / (1.0f + __expf(-v)); }
__device__ __forceinline__ float tanh_(float v) { return 2.0f / (1.0f + __expf(-2.0f * v)) - 1.0f; }

// Packed fp32x2 FMA (SASS FFMA2)
__device__ __forceinline__ void ffma2(u64 &d, u64 a, u64 b) {
    asm("fma.rn.f32x2 %0, %1, %2, %0;" : "+l"(d) : "l"(a), "l"(b));
}
__device__ __forceinline__ float fold2(u64 p) {
    float2 f = *reinterpret_cast<float2*>(&p);
    return f.x + f.y;
}
__device__ __forceinline__ void cpa16(u32 d, const void* s) {
    asm volatile("cp.async.cg.shared.global [%0], [%1], 16;" :: "r"(d), "l"(s));
}
__device__ __forceinline__ void cpcommit() { asm volatile("cp.async.commit_group;"); }
template<int N> __device__ __forceinline__ void cpwait() {
    asm volatile("cp.async.wait_group %0;" :: "n"(N));
}

__global__ void init_kernel(const float* __restrict__ init_state) {
    int i = blockIdx.x * blockDim.x + threadIdx.x;
    if (i == 0) g_bar = 0u;
    if (i < LL * BB * HH) {
        int l = i / (BB * HH);
        int r = i - l * (BB * HH);
        g_c[i]    = init_state[(l * 2 + 0) * (BB * HH) + r];
        float h   = init_state[(l * 2 + 1) * (BB * HH) + r];
        g_h[0][i] = h;
        g_h[1][i] = h;
    }
}

// Pre-swizzle W into per-tile smem layout: [nh][chunk(8)][k2(32)][g*32+hc] float2
__global__ void prep_kernel(const float* __restrict__ W) {
    int idx = blockIdx.x * blockDim.x + threadIdx.x;   // float2 index
    if (idx >= 8 * 8 * 32 * 128) return;
    int col = idx & 127;           // g*32 + hc
    int k2  = (idx >> 7) & 31;
    int c   = (idx >> 12) & 7;
    int nh  = idx >> 15;           // nh block
    int k   = c * KC + (k2 << 1);
    int gcol = (col >> 5) * 256 + nh * 32 + (col & 31);
    g_Wpack[idx * 2]     = W[(size_t)k * 1024 + gcol];
    g_Wpack[idx * 2 + 1] = W[(size_t)(k + 1) * 1024 + gcol];
}

// Stage one W chunk (32KB) into stage s: 64B per thread = 4 cp.async.
__device__ __forceinline__ void issueW(u32 sbase, int nh, int c, int s, int tid) {
    const float* wsrc = g_Wpack + ((size_t)(nh * 8 + c) << 13) + tid * 16;
    u32 dst = sbase + s * STAGE_BYTES + (u32)tid * 64;
    cpa16(dst, wsrc);
    cpa16(dst + 16, wsrc + 4);
    cpa16(dst + 32, wsrc + 8);
    cpa16(dst + 48, wsrc + 12);
}

// Per-tile body. 16 warps split as NRG row-groups x NKS k-segments.
// NKS=4 (CG<=2): W crossbar traffic halved vs NKS=2.  NKS=2 (CG>=3): reg-bounded.
template<int CG, int NKS>
__device__ __forceinline__ void tile_body(
    char* smem, const float* __restrict__ x,
    const float* __restrict__ bias, float* __restrict__ out,
    const float* __restrict__ hin, float* __restrict__ hout,
    int d, int l_lo, int l_hi, int tile)
{
    constexpr int NRG = 16 / NKS;           // row-groups
    constexpr int RWX = 16 * CG / NRG;      // rows per warp
    constexpr int KQ  = 32 / NKS;           // k2 per segment
    constexpr int SEG = 16 * CG * 128;      // xch floats per partial set
    const int tid = threadIdx.x;
    const int w   = tid >> 5;
    const int hc  = tid & 31;
    const int nh      = tile & 7;
    const int nh0     = nh << 5;
    const int l_base  = l_lo + (tile >> 3) * CG;

    // --- A source pointers (1 row per thread, clamped so always valid) ---
    const int s_row = tid >> 3;
    const int p8    = (tid & 7) << 3;     // float offset within row
    const int ci_s  = s_row >> 4;
    const int bb_s  = s_row & 15;
    int ls = l_base + ci_s; if (ls > l_hi) ls = l_hi;
    const int ts = d - ls;
    const float* pin = ((ls == 0) ? (x + (bb_s * TT + ts) * HH)
                                  : (hin + ((ls - 1) * BB + bb_s) * HH)) + p8;
    const float* ph  = hin + (ls * BB + bb_s) * HH + p8;

    const u32 sbase = (u32)__cvta_generic_to_shared(smem);
    const u32 a_dst = sbase + A_OFF + (s_row << 8) + ((tid & 7) << 5);

    // --- issue A chunks 0,1 into stages 0,1 (W0,W1 already in flight pre-barrier) ---
    cpa16(a_dst, pin);                    cpa16(a_dst + 16, pin + 4);                    cpcommit();
    cpa16(a_dst + STAGE_BYTES, pin + KC); cpa16(a_dst + STAGE_BYTES + 16, pin + KC + 4); cpcommit();

    u64 acc[RWX][4];
    #pragma unroll
    for (int j = 0; j < RWX; j++)
        #pragma unroll
        for (int g = 0; g < 4; g++) acc[j][g] = 0ull;

    const int rg = w % NRG;
    const int ks = w / NRG;
    const int r0     = rg * RWX;
    const int k2base = ks * KQ;

    // --- K mainloop: 8 chunks, 3-stage ring, lookahead 2 ---
    #pragma unroll 1
    for (int c = 0; c < NCHUNK; c++) {
        cpwait<1>();
        __syncthreads();                 // chunk c visible; all warps done with c-1
        if (c + 2 < NCHUNK) {
            const int nc = c + 2;
            const int sn = nc % 3;
            issueW(sbase, nh, nc, sn, tid);
            const float* asrc = ((nc & 4) ? ph : pin) + (nc & 3) * KC;
            u32 ad = a_dst + sn * STAGE_BYTES;
            cpa16(ad, asrc); cpa16(ad + 16, asrc + 4);
        }
        cpcommit();
        const int s = c % 3;
        const float* a = (const float*)(smem + s * STAGE_BYTES + A_OFF) + r0 * KC;
        const float2* w2 = (const float2*)(smem + s * STAGE_BYTES) + hc;
        #pragma unroll
        for (int q = 0; q < KQ; q++) {
            const int k2 = k2base + q;
            u64 wv[4];
            #pragma unroll
            for (int g = 0; g < 4; g++)
                wv[g] = *reinterpret_cast<const u64*>(w2 + k2 * 128 + g * 32);
            #pragma unroll
            for (int j = 0; j < RWX; j++) {
                u64 ap = *reinterpret_cast<const u64*>(a + j * KC + (k2 << 1));
                #pragma unroll
                for (int g = 0; g < 4; g++)
                    ffma2(acc[j][g], ap, wv[g]);
            }
        }
    }

    // --- combine k-segments (xch overlays stage-2 region; quiescent after c=7) ---
    __syncthreads();
    float* xch = (float*)(smem + 2 * STAGE_BYTES);   // (NKS-1)*SEG floats <= 48KB
    if (ks > 0) {
        float* xs = xch + (ks - 1) * SEG + r0 * 128 + hc;
        #pragma unroll
        for (int j = 0; j < RWX; j++)
            #pragma unroll
            for (int g = 0; g < 4; g++)
                xs[j * 128 + g * 32] = fold2(acc[j][g]);
    }
    __syncthreads();
    if (ks == 0) {
        const int hcol = nh0 + hc;
        const float bi = bias[hcol];
        const float bj = bias[256 + hcol];
        const float bf = bias[512 + hcol];
        const float bo = bias[768 + hcol];
        #pragma unroll
        for (int j = 0; j < RWX; j++) {
            const int row = r0 + j;
            const int ci  = row >> 4;
            const int bb  = row & 15;
            const int l   = l_base + ci;
            if (l <= l_hi) {
                const int t    = d - l;
                const int sidx = (l * BB + bb) * HH + hcol;
                float z[4];
                #pragma unroll
                for (int g = 0; g < 4; g++) z[g] = fold2(acc[j][g]);
                #pragma unroll
                for (int seg = 0; seg < NKS - 1; seg++) {
                    const float* xr = xch + seg * SEG + row * 128 + hc;
                    #pragma unroll
                    for (int g = 0; g < 4; g++) z[g] += xr[g * 32];
                }
                float zi = z[0] + bi;
                float zj = z[1] + bj;
                float zf = z[2] + bf;
                float zo = z[3] + bo;
                float cold = g_c[sidx];
                float ncv  = sig_(zf + 1.0f) * cold + sig_(zi) * tanh_(zj);
                float nhv  = sig_(zo) * tanh_(ncv);
                g_c[sidx]  = ncv;
                hout[sidx] = nhv;
                if (l == LL - 1) out[(bb * TT + t) * HH + hcol] = nhv;
            }
        }
    }
}

__global__ void __launch_bounds__(NTHREADS, 1)
lstm_kernel(const float* __restrict__ x, const float* __restrict__ bias,
            float* __restrict__ out) {
    extern __shared__ __align__(16) char smem[];
    const int tid = threadIdx.x;
    const int G   = gridDim.x;
    const u32 sbase = (u32)__cvta_generic_to_shared(smem);

    // --- prologue: prefetch W chunks 0,1 for d=0 (ntiles=8) ---
    {
        const bool act = (blockIdx.x < 8);
        if (act) issueW(sbase, blockIdx.x & 7, 0, 0, tid);
        cpcommit();
        if (act) issueW(sbase, blockIdx.x & 7, 1, 1, tid);
        cpcommit();
    }

    for (int d = 0; d < NDIAG; d++) {
        const int l_lo = (d - (TT - 1) > 0) ? d - (TT - 1) : 0;
        const int l_hi = (d < LL - 1) ? d : LL - 1;
        const int n    = l_hi - l_lo + 1;
        const int CG   = (n + 17) / 18;          // 1..4 cells per M-tile
        const int ngroups = (n + CG - 1) / CG;
        const int ntiles  = ngroups << 3;        // <= 144
        const float* hin  = g_h[(d + 1) & 1];
        float*       hout = g_h[d & 1];

        if ((int)blockIdx.x < ntiles) {
            const int tile = blockIdx.x;
            if      (CG == 4) tile_body<4, 2>(smem, x, bias, out, hin, hout, d, l_lo, l_hi, tile);
            else if (CG == 3) tile_body<3, 2>(smem, x, bias, out, hin, hout, d, l_lo, l_hi, tile);
            else if (CG == 2) tile_body<2, 4>(smem, x, bias, out, hin, hout, d, l_lo, l_hi, tile);
            else              tile_body<1, 4>(smem, x, bias, out, hin, hout, d, l_lo, l_hi, tile);
        }

        if (d < NDIAG - 1) {
            // --- cross-barrier W prefetch for next diagonal (state-independent) ---
            const int d2    = d + 1;
            const int l_lo2 = (d2 - (TT - 1) > 0) ? d2 - (TT - 1) : 0;
            const int l_hi2 = (d2 < LL - 1) ? d2 : LL - 1;
            const int n2    = l_hi2 - l_lo2 + 1;
            const int CG2   = (n2 + 17) / 18;
            const int ntiles2 = ((n2 + CG2 - 1) / CG2) << 3;
            const bool actN = ((int)blockIdx.x < ntiles2);
            if (actN) issueW(sbase, blockIdx.x & 7, 0, 0, tid);
            cpcommit();
            if (actN) issueW(sbase, blockIdx.x & 7, 1, 1, tid);
            cpcommit();

            // --- grid-wide barrier (release + L1 invalidate via membar.gpu) ---
            __threadfence();
            __syncthreads();
            if (tid == 0) {
                unsigned target = (unsigned)G * (unsigned)(d + 1);
                atomicAdd(&g_bar, 1u);
                while (*((volatile unsigned*)&g_bar) < target) { }
            }
            __syncthreads();
        }
    }
}

extern "C" void kernel_launch(void* const* d_in, const int* in_sizes, int n_in,
                              void* d_out, int out_size) {
    const float* x    = (const float*)d_in[0];   // (B, T, H)
    const float* init = (const float*)d_in[1];   // (L, 2, B, H)
    const float* W    = (const float*)d_in[2];   // (2H, 4H)
    const float* bias = (const float*)d_in[3];   // (4H,)
    float* out        = (float*)d_out;           // (B, T, H)

    cudaFuncSetAttribute(lstm_kernel, cudaFuncAttributeMaxDynamicSharedMemorySize, SMEM_TOTAL);
    init_kernel<<<(LL * BB * HH + 255) / 256, 256>>>(init);
    prep_kernel<<<(8 * 8 * 32 * 128 + 255) / 256, 256>>>(W);
    lstm_kernel<<<GRID, NTHREADS, SMEM_TOTAL>>>(x, bias, out);
}